// round 4
// baseline (speedup 1.0000x reference)
#include <cuda_runtime.h>

typedef unsigned long long ull;

// Problem shapes (fixed by setup_inputs)
#define Hh   256
#define Kk   4096
#define Nn   256    // S*S
#define DD   2048   // D = H*d
#define QB   128    // queries per block
#define NPAIR 2048  // K/2 codeword pairs
#define ROWB 80     // bytes per ct row: 64B interleaved pair data + 8B half-norms + 8B pad

#define CT_BYTES   (NPAIR * ROWB)          // 163840
#define XS_OFF     CT_BYTES
#define XS_BYTES   (QB * 64)               // 8192: per query 8 dup-f32x2 (negated)
#define PART_OFF   (XS_OFF + XS_BYTES)
#define PART_BYTES (16 * QB * 8)           // 16384: [krange][qid] = {best, k}
#define SMEM_TOTAL (PART_OFF + PART_BYTES) // 188416

__device__ __forceinline__ ull ffma2(ull a, ull b, ull c) {
    ull d;
    asm("fma.rn.f32x2 %0, %1, %2, %3;" : "=l"(d) : "l"(a), "l"(b), "l"(c));
    return d;
}

__device__ __forceinline__ void score_pair(const ull* xr, const char* row,
                                           float& lo, float& hi) {
    ulonglong2 cA = ((const ulonglong2*)row)[0];
    ulonglong2 cB = ((const ulonglong2*)row)[1];
    ulonglong2 cC = ((const ulonglong2*)row)[2];
    ulonglong2 cD = ((const ulonglong2*)row)[3];
    ull ch = *((const ull*)(row + 64));
    ull acc = ffma2(xr[0], cA.x, ch);
    acc = ffma2(xr[1], cA.y, acc);
    acc = ffma2(xr[2], cB.x, acc);
    acc = ffma2(xr[3], cB.y, acc);
    acc = ffma2(xr[4], cC.x, acc);
    acc = ffma2(xr[5], cC.y, acc);
    acc = ffma2(xr[6], cD.x, acc);
    acc = ffma2(xr[7], cD.y, acc);
    lo = __uint_as_float((unsigned)acc);
    hi = __uint_as_float((unsigned)(acc >> 32));
}

__global__ __launch_bounds__(512)
void vq_kernel(const float* __restrict__ emb,
               const float* __restrict__ cb,
               float* __restrict__ out) {
    extern __shared__ char smem[];
    const int h  = blockIdx.x >> 2;
    const int qc = blockIdx.x & 3;
    const int tid = threadIdx.x;

    // ---- stage queries: xs[j][dd] = {-x, -x} (duplicated for packed FMA) ----
    float* xs = (float*)(smem + XS_OFF);
    for (int i = tid; i < QB * 8; i += 512) {
        int j = i >> 3, dd = i & 7;
        int g = qc * QB + j;
        int b = g >> 8, n = g & 255;
        float v = emb[((size_t)(b * DD + h * 8 + dd)) * Nn + n];
        ((float2*)xs)[j * 8 + dd] = make_float2(-v, -v);
    }

    // ---- stage codebook: ct[kp] row = 8 x {c[2kp][dd], c[2kp+1][dd]} + {hc0, hc1} ----
    char* ct = smem;
    const float4* csrc = (const float4*)(cb + (size_t)h * Kk * 8);
    for (int kp = tid; kp < NPAIR; kp += 512) {
        float4 a0 = csrc[kp * 4 + 0];
        float4 a1 = csrc[kp * 4 + 1];
        float4 a2 = csrc[kp * 4 + 2];
        float4 a3 = csrc[kp * 4 + 3];
        float s0 = a0.x * a0.x;
        s0 = fmaf(a0.y, a0.y, s0); s0 = fmaf(a0.z, a0.z, s0); s0 = fmaf(a0.w, a0.w, s0);
        s0 = fmaf(a1.x, a1.x, s0); s0 = fmaf(a1.y, a1.y, s0); s0 = fmaf(a1.z, a1.z, s0);
        s0 = fmaf(a1.w, a1.w, s0);
        float s1 = a2.x * a2.x;
        s1 = fmaf(a2.y, a2.y, s1); s1 = fmaf(a2.z, a2.z, s1); s1 = fmaf(a2.w, a2.w, s1);
        s1 = fmaf(a3.x, a3.x, s1); s1 = fmaf(a3.y, a3.y, s1); s1 = fmaf(a3.z, a3.z, s1);
        s1 = fmaf(a3.w, a3.w, s1);
        char* row = ct + kp * ROWB;
        ((float4*)row)[0] = make_float4(a0.x, a2.x, a0.y, a2.y);
        ((float4*)row)[1] = make_float4(a0.z, a2.z, a0.w, a2.w);
        ((float4*)row)[2] = make_float4(a1.x, a3.x, a1.y, a3.y);
        ((float4*)row)[3] = make_float4(a1.z, a3.z, a1.w, a3.w);
        *((float2*)(row + 64)) = make_float2(s0 * 0.5f, s1 * 0.5f);
    }
    __syncthreads();

    // ---- main scan: warp w covers pairs [w*128, (w+1)*128), all 128 queries ----
    // Lane carries QR=4 queries: q = lane + 32*qr.
    const int w = tid >> 5, lane = tid & 31;

    ull xr[4][8];
#pragma unroll
    for (int q = 0; q < 4; q++) {
        const ulonglong2* xrow = (const ulonglong2*)(xs + (lane + (q << 5)) * 16);
#pragma unroll
        for (int t = 0; t < 4; t++) {
            ulonglong2 v = xrow[t];
            xr[q][2 * t]     = v.x;
            xr[q][2 * t + 1] = v.y;
        }
    }

    float best[4];
    int   bp[4];
#pragma unroll
    for (int q = 0; q < 4; q++) { best[q] = 3.4028234663852886e38f; bp[q] = w << 7; }

    const char* row = ct + (size_t)(w << 7) * ROWB;
    // Preload first row (software pipeline)
    ulonglong2 cA = ((const ulonglong2*)row)[0];
    ulonglong2 cB = ((const ulonglong2*)row)[1];
    ulonglong2 cC = ((const ulonglong2*)row)[2];
    ulonglong2 cD = ((const ulonglong2*)row)[3];
    ull ch = *((const ull*)(row + 64));

#pragma unroll 1
    for (int kp = 0; kp < 128; kp++) {
        // Prefetch next row (last iter overreads 72B into xs region — in-bounds, unused)
        const char* nrow = row + ROWB;
        ulonglong2 nA = ((const ulonglong2*)nrow)[0];
        ulonglong2 nB = ((const ulonglong2*)nrow)[1];
        ulonglong2 nC = ((const ulonglong2*)nrow)[2];
        ulonglong2 nD = ((const ulonglong2*)nrow)[3];
        ull nh = *((const ull*)(nrow + 64));

#pragma unroll
        for (int q = 0; q < 4; q++) {
            ull acc = ffma2(xr[q][0], cA.x, ch);
            acc = ffma2(xr[q][1], cA.y, acc);
            acc = ffma2(xr[q][2], cB.x, acc);
            acc = ffma2(xr[q][3], cB.y, acc);
            acc = ffma2(xr[q][4], cC.x, acc);
            acc = ffma2(xr[q][5], cC.y, acc);
            acc = ffma2(xr[q][6], cD.x, acc);
            acc = ffma2(xr[q][7], cD.y, acc);
            float m = fminf(__uint_as_float((unsigned)acc),
                            __uint_as_float((unsigned)(acc >> 32)));
            if (m < best[q]) { best[q] = m; bp[q] = (w << 7) + kp; }
        }

        cA = nA; cB = nB; cC = nC; cD = nD; ch = nh;
        row = nrow;
    }

    // ---- resolve lo/hi half of winning pair (once per lane per q) ----
    float2* part = (float2*)(smem + PART_OFF);
#pragma unroll
    for (int q = 0; q < 4; q++) {
        float lo, hi;
        score_pair(xr[q], ct + (size_t)bp[q] * ROWB, lo, hi);
        int k = bp[q] * 2 + ((hi < lo) ? 1 : 0);
        part[(w << 7) + lane + (q << 5)] = make_float2(best[q], __int_as_float(k));
    }
    __syncthreads();

    // ---- merge across k-ranges (ascending w => first-index tie-break preserved) ----
    if (tid < QB) {
        float2 p = part[tid];
        float bb = p.x;
        int   bi = __float_as_int(p.y);
#pragma unroll
        for (int ww = 1; ww < 16; ww++) {
            float2 c2 = part[(ww << 7) + tid];
            if (c2.x < bb) { bb = c2.x; bi = __float_as_int(c2.y); }
        }
        int g = qc * QB + tid;
        int b = g >> 8, n = g & 255;
        const char* crow = ct + (size_t)(bi >> 1) * ROWB;
        int hs = bi & 1;
#pragma unroll
        for (int dd = 0; dd < 8; dd++) {
            float qv = ((const float*)crow)[dd * 2 + hs];
            float xv = -xs[tid * 16 + dd * 2];              // stored as -x
            out[((size_t)(b * DD + h * 8 + dd)) * Nn + n] = xv + (qv - xv); // mimic ref rounding
        }
    }
}

extern "C" void kernel_launch(void* const* d_in, const int* in_sizes, int n_in,
                              void* d_out, int out_size) {
    const float* emb = (const float*)d_in[0];
    const float* cb  = (const float*)d_in[1];
    float* out = (float*)d_out;
    cudaFuncSetAttribute(vq_kernel, cudaFuncAttributeMaxDynamicSharedMemorySize, SMEM_TOTAL);
    vq_kernel<<<Hh * 4, 512, SMEM_TOTAL>>>(emb, cb, out);
}

// round 5
// speedup vs baseline: 1.0010x; 1.0010x over previous
#include <cuda_runtime.h>

typedef unsigned long long ull;

// Problem shapes (fixed by setup_inputs)
#define Hh   256
#define Kk   4096
#define Nn   256    // S*S
#define DD   2048   // D = H*d
#define QB   128    // queries per block
#define NPAIR 2048  // K/2 codeword pairs
#define ROWB 80     // bytes per ct row: 64B interleaved pair data + 8B half-norms + 8B pad

#define CT_BYTES   (NPAIR * ROWB)          // 163840
#define XS_OFF     CT_BYTES
#define XS_BYTES   (QB * 64)               // 8192: per query 8 dup-f32x2 (negated)
#define PART_OFF   (XS_OFF + XS_BYTES)
#define PART_BYTES (16 * QB * 8)           // 16384: [krange][qid] = {best, k}
#define SMEM_TOTAL (PART_OFF + PART_BYTES) // 188416

__device__ __forceinline__ ull ffma2(ull a, ull b, ull c) {
    ull d;
    asm("fma.rn.f32x2 %0, %1, %2, %3;" : "=l"(d) : "l"(a), "l"(b), "l"(c));
    return d;
}

__device__ __forceinline__ void score_pair(const ull* xr, const char* row,
                                           float& lo, float& hi) {
    ulonglong2 cA = ((const ulonglong2*)row)[0];
    ulonglong2 cB = ((const ulonglong2*)row)[1];
    ulonglong2 cC = ((const ulonglong2*)row)[2];
    ulonglong2 cD = ((const ulonglong2*)row)[3];
    ull ch = *((const ull*)(row + 64));
    ull acc = ffma2(xr[0], cA.x, ch);
    acc = ffma2(xr[1], cA.y, acc);
    acc = ffma2(xr[2], cB.x, acc);
    acc = ffma2(xr[3], cB.y, acc);
    acc = ffma2(xr[4], cC.x, acc);
    acc = ffma2(xr[5], cC.y, acc);
    acc = ffma2(xr[6], cD.x, acc);
    acc = ffma2(xr[7], cD.y, acc);
    lo = __uint_as_float((unsigned)acc);
    hi = __uint_as_float((unsigned)(acc >> 32));
}

__global__ __launch_bounds__(512)
void vq_kernel(const float* __restrict__ emb,
               const float* __restrict__ cb,
               float* __restrict__ out) {
    extern __shared__ char smem[];
    const int h  = blockIdx.x >> 2;
    const int qc = blockIdx.x & 3;
    const int tid = threadIdx.x;

    // ---- stage queries: xs[j][dd] = {-x, -x} (duplicated for packed FMA) ----
    float* xs = (float*)(smem + XS_OFF);
    for (int i = tid; i < QB * 8; i += 512) {
        int j = i >> 3, dd = i & 7;
        int g = qc * QB + j;
        int b = g >> 8, n = g & 255;
        float v = emb[((size_t)(b * DD + h * 8 + dd)) * Nn + n];
        ((float2*)xs)[j * 8 + dd] = make_float2(-v, -v);
    }

    // ---- stage codebook: ct[kp] row = 8 x {c[2kp][dd], c[2kp+1][dd]} + {hc0, hc1} ----
    char* ct = smem;
    const float4* csrc = (const float4*)(cb + (size_t)h * Kk * 8);
    for (int kp = tid; kp < NPAIR; kp += 512) {
        float4 a0 = csrc[kp * 4 + 0];
        float4 a1 = csrc[kp * 4 + 1];
        float4 a2 = csrc[kp * 4 + 2];
        float4 a3 = csrc[kp * 4 + 3];
        float s0 = a0.x * a0.x;
        s0 = fmaf(a0.y, a0.y, s0); s0 = fmaf(a0.z, a0.z, s0); s0 = fmaf(a0.w, a0.w, s0);
        s0 = fmaf(a1.x, a1.x, s0); s0 = fmaf(a1.y, a1.y, s0); s0 = fmaf(a1.z, a1.z, s0);
        s0 = fmaf(a1.w, a1.w, s0);
        float s1 = a2.x * a2.x;
        s1 = fmaf(a2.y, a2.y, s1); s1 = fmaf(a2.z, a2.z, s1); s1 = fmaf(a2.w, a2.w, s1);
        s1 = fmaf(a3.x, a3.x, s1); s1 = fmaf(a3.y, a3.y, s1); s1 = fmaf(a3.z, a3.z, s1);
        s1 = fmaf(a3.w, a3.w, s1);
        char* row = ct + kp * ROWB;
        ((float4*)row)[0] = make_float4(a0.x, a2.x, a0.y, a2.y);
        ((float4*)row)[1] = make_float4(a0.z, a2.z, a0.w, a2.w);
        ((float4*)row)[2] = make_float4(a1.x, a3.x, a1.y, a3.y);
        ((float4*)row)[3] = make_float4(a1.z, a3.z, a1.w, a3.w);
        *((float2*)(row + 64)) = make_float2(s0 * 0.5f, s1 * 0.5f);
    }
    __syncthreads();

    // ---- main scan: warp w covers pairs [w*128, (w+1)*128), all 128 queries ----
    // Lane carries QR=4 queries: q = lane + 32*qr.
    const int w = tid >> 5, lane = tid & 31;

    ull xr[4][8];
#pragma unroll
    for (int q = 0; q < 4; q++) {
        const ulonglong2* xrow = (const ulonglong2*)(xs + (lane + (q << 5)) * 16);
#pragma unroll
        for (int t = 0; t < 4; t++) {
            ulonglong2 v = xrow[t];
            xr[q][2 * t]     = v.x;
            xr[q][2 * t + 1] = v.y;
        }
    }

    float best[4];
    int   bp[4];
#pragma unroll
    for (int q = 0; q < 4; q++) { best[q] = 3.4028234663852886e38f; bp[q] = w << 7; }

    const char* row = ct + (size_t)(w << 7) * ROWB;
    // Preload first row (software pipeline)
    ulonglong2 cA = ((const ulonglong2*)row)[0];
    ulonglong2 cB = ((const ulonglong2*)row)[1];
    ulonglong2 cC = ((const ulonglong2*)row)[2];
    ulonglong2 cD = ((const ulonglong2*)row)[3];
    ull ch = *((const ull*)(row + 64));

#pragma unroll 1
    for (int kp = 0; kp < 128; kp++) {
        // Prefetch next row (last iter overreads 72B into xs region — in-bounds, unused)
        const char* nrow = row + ROWB;
        ulonglong2 nA = ((const ulonglong2*)nrow)[0];
        ulonglong2 nB = ((const ulonglong2*)nrow)[1];
        ulonglong2 nC = ((const ulonglong2*)nrow)[2];
        ulonglong2 nD = ((const ulonglong2*)nrow)[3];
        ull nh = *((const ull*)(nrow + 64));

#pragma unroll
        for (int q = 0; q < 4; q++) {
            ull acc = ffma2(xr[q][0], cA.x, ch);
            acc = ffma2(xr[q][1], cA.y, acc);
            acc = ffma2(xr[q][2], cB.x, acc);
            acc = ffma2(xr[q][3], cB.y, acc);
            acc = ffma2(xr[q][4], cC.x, acc);
            acc = ffma2(xr[q][5], cC.y, acc);
            acc = ffma2(xr[q][6], cD.x, acc);
            acc = ffma2(xr[q][7], cD.y, acc);
            float m = fminf(__uint_as_float((unsigned)acc),
                            __uint_as_float((unsigned)(acc >> 32)));
            if (m < best[q]) { best[q] = m; bp[q] = (w << 7) + kp; }
        }

        cA = nA; cB = nB; cC = nC; cD = nD; ch = nh;
        row = nrow;
    }

    // ---- resolve lo/hi half of winning pair (once per lane per q) ----
    float2* part = (float2*)(smem + PART_OFF);
#pragma unroll
    for (int q = 0; q < 4; q++) {
        float lo, hi;
        score_pair(xr[q], ct + (size_t)bp[q] * ROWB, lo, hi);
        int k = bp[q] * 2 + ((hi < lo) ? 1 : 0);
        part[(w << 7) + lane + (q << 5)] = make_float2(best[q], __int_as_float(k));
    }
    __syncthreads();

    // ---- merge across k-ranges (ascending w => first-index tie-break preserved) ----
    if (tid < QB) {
        float2 p = part[tid];
        float bb = p.x;
        int   bi = __float_as_int(p.y);
#pragma unroll
        for (int ww = 1; ww < 16; ww++) {
            float2 c2 = part[(ww << 7) + tid];
            if (c2.x < bb) { bb = c2.x; bi = __float_as_int(c2.y); }
        }
        int g = qc * QB + tid;
        int b = g >> 8, n = g & 255;
        const char* crow = ct + (size_t)(bi >> 1) * ROWB;
        int hs = bi & 1;
#pragma unroll
        for (int dd = 0; dd < 8; dd++) {
            float qv = ((const float*)crow)[dd * 2 + hs];
            float xv = -xs[tid * 16 + dd * 2];              // stored as -x
            out[((size_t)(b * DD + h * 8 + dd)) * Nn + n] = xv + (qv - xv); // mimic ref rounding
        }
    }
}

extern "C" void kernel_launch(void* const* d_in, const int* in_sizes, int n_in,
                              void* d_out, int out_size) {
    const float* emb = (const float*)d_in[0];
    const float* cb  = (const float*)d_in[1];
    float* out = (float*)d_out;
    cudaFuncSetAttribute(vq_kernel, cudaFuncAttributeMaxDynamicSharedMemorySize, SMEM_TOTAL);
    vq_kernel<<<Hh * 4, 512, SMEM_TOTAL>>>(emb, cb, out);
}